// round 11
// baseline (speedup 1.0000x reference)
#include <cuda_runtime.h>
#include <cstdint>

// key = ((x*64+y)*64+z)*64+b  in [0, 2^24)
constexpr int KEYSPACE     = 1 << 24;
constexpr int WORDS        = KEYSPACE / 32;                 // 524288
constexpr int SCAN_THREADS = 256;                           // 4 words/thread
constexpr int SCAN_TILES   = WORDS / (4 * SCAN_THREADS);    // 512 (== k_build grid)
constexpr int PPT          = 8;      // points per thread in setbits phase
constexpr int PAD_BLOCKS   = 128;    // pad-zero blocks appended to scatter grid
constexpr int EXR_BLOCKS   = 32;     // extras-rank blocks appended to scatter grid
constexpr int EX_BLOCKS    = 256;    // extras red kernel
constexpr unsigned KEYMASK   = 0x00FFFFFFu;
constexpr unsigned EXTRA_BIT = 0x80000000u;

__device__ unsigned g_bitmap[WORDS];             // presence bits (self-cleaned by scan)
__device__ uint2    g_tab[WORDS];                // {bits, rank}
__device__ unsigned g_key[1 << 20];              // per-point key | EXTRA_BIT
__device__ uint2    g_ex[1 << 20];               // {point index, rank} of non-owner dups
__device__ unsigned long long g_desc[SCAN_TILES];// lookback descriptors (reset in scatter)
__device__ unsigned g_extra_cnt;                 // reset by extras epilogue
__device__ unsigned g_done;                      // extras completion counter
__device__ unsigned g_bar;                       // grid barrier for k_build
__device__ unsigned g_total;                     // unique voxel count

// ---------------------------------------------------------------------------
__device__ __forceinline__ unsigned make_key(int4 c) {
    return ((unsigned)((c.x * 64 + c.y) * 64 + c.z)) * 64u + (unsigned)c.w;
}

__device__ __forceinline__ unsigned long long ld_relaxed(const unsigned long long* p) {
    unsigned long long v;
    asm volatile("ld.relaxed.gpu.global.u64 %0, [%1];" : "=l"(v) : "l"(p) : "memory");
    return v;
}

__device__ __forceinline__ unsigned ld_acquire(const unsigned* p) {
    unsigned v;
    asm volatile("ld.acquire.gpu.global.u32 %0, [%1];" : "=r"(v) : "l"(p) : "memory");
    return v;
}

__device__ __forceinline__ unsigned block_excl_scan(unsigned v, unsigned* sh) {
    unsigned lane = threadIdx.x & 31;
    unsigned wid  = threadIdx.x >> 5;
    unsigned x = v;
    #pragma unroll
    for (int o = 1; o < 32; o <<= 1) {
        unsigned y = __shfl_up_sync(0xFFFFFFFFu, x, o);
        if (lane >= o) x += y;
    }
    if (lane == 31) sh[wid] = x;
    __syncthreads();
    if (wid == 0) {
        unsigned nw = blockDim.x >> 5;
        unsigned w2 = (lane < nw) ? sh[lane] : 0u;
        #pragma unroll
        for (int o = 1; o < 32; o <<= 1) {
            unsigned y = __shfl_up_sync(0xFFFFFFFFu, w2, o);
            if (lane >= o) w2 += y;
        }
        if (lane < nw) sh[lane] = w2;
    }
    __syncthreads();
    unsigned warp_prefix = (wid > 0) ? sh[wid - 1] : 0u;
    return warp_prefix + x - v;   // exclusive
}

// ---------------------------------------------------------------------------
// Fused: setbits (8-way atomic MLP) -> software grid barrier -> scan.
// Grid MUST be exactly SCAN_TILES blocks; all co-resident (512 <= 148*8).
__global__ void __launch_bounds__(SCAN_THREADS, 8)
k_build(const int4* __restrict__ coords, int n) {
    // ---------- phase 1: claim voxels, record keys + extras ----------
    int gtid   = blockIdx.x * SCAN_THREADS + threadIdx.x;
    int nthr   = SCAN_TILES * SCAN_THREADS;           // 131072
    for (int base = gtid * PPT; base < n; base += nthr * PPT) {
        // 1) load all coords, compute keys (independent loads, MLP=8)
        unsigned k[PPT];
        #pragma unroll
        for (int j = 0; j < PPT; j++) {
            int i = base + j;
            k[j] = (i < n) ? make_key(__ldg(&coords[i])) : 0xFFFFFFFFu;
        }
        // 2) fire all atomics back-to-back (MLP=8)
        unsigned old[PPT];
        #pragma unroll
        for (int j = 0; j < PPT; j++) {
            if (k[j] != 0xFFFFFFFFu)
                old[j] = atomicOr(&g_bitmap[k[j] >> 5], 1u << (k[j] & 31));
        }
        // 3) post-process: flag dups, append extras
        #pragma unroll
        for (int j = 0; j < PPT; j++) {
            if (k[j] != 0xFFFFFFFFu && (old[j] & (1u << (k[j] & 31)))) {
                k[j] |= EXTRA_BIT;
                g_ex[atomicAdd(&g_extra_cnt, 1u)].x = (unsigned)(base + j);
            }
        }
        // 4) store keys (two 16B stores when fully in-bounds)
        if (base + PPT <= n) {
            uint4* kp = reinterpret_cast<uint4*>(&g_key[base]);
            kp[0] = make_uint4(k[0], k[1], k[2], k[3]);
            kp[1] = make_uint4(k[4], k[5], k[6], k[7]);
        } else {
            for (int j = 0; j < PPT; j++)
                if (base + j < n) g_key[base + j] = k[j];
        }
    }

    // ---------- grid barrier (release-add / acquire-spin) ----------
    __syncthreads();
    if (threadIdx.x == 0) {
        unsigned one = 1u;
        asm volatile("red.release.gpu.global.add.u32 [%0], %1;"
                     :: "l"(&g_bar), "r"(one) : "memory");
        while (ld_acquire(&g_bar) < (unsigned)gridDim.x) { }
    }
    __syncthreads();

    // ---------- phase 2: prefix-popcount scan (tile == blockIdx.x) ----------
    __shared__ unsigned sh[32];
    __shared__ unsigned sh_total, sh_prefix;
    unsigned tile = blockIdx.x;
    unsigned t = tile * SCAN_THREADS + threadIdx.x;       // uint4 index
    uint4 w = reinterpret_cast<const uint4*>(g_bitmap)[t];
    reinterpret_cast<uint4*>(g_bitmap)[t] = make_uint4(0u, 0u, 0u, 0u); // self-clean
    unsigned p0 = __popc(w.x), p1 = __popc(w.y), p2 = __popc(w.z), p3 = __popc(w.w);
    unsigned sum  = p0 + p1 + p2 + p3;
    unsigned excl = block_excl_scan(sum, sh);
    if (threadIdx.x == SCAN_THREADS - 1) sh_total = excl + sum;
    __syncthreads();
    unsigned T = sh_total;

    if (threadIdx.x < 32) {
        unsigned lane = threadIdx.x;
        unsigned prefix = 0;
        if (tile == 0) {
            if (lane == 0) {
                atomicExch(&g_desc[0], (2ull << 32) | (unsigned long long)T);
                sh_prefix = 0u;
            }
        } else {
            if (lane == 0)
                atomicExch(&g_desc[tile], (1ull << 32) | (unsigned long long)T);
            int base = (int)tile - 1;
            while (true) {
                int j = base - (int)lane;
                unsigned long long d = (j >= 0) ? ld_relaxed(&g_desc[j]) : (2ull << 32);
                unsigned st = (unsigned)(d >> 32);
                unsigned m2 = __ballot_sync(0xFFFFFFFFu, st == 2u);
                unsigned m0 = __ballot_sync(0xFFFFFFFFu, st == 0u);
                int c2 = m2 ? (__ffs(m2) - 1) : 32;
                int c0 = m0 ? (__ffs(m0) - 1) : 32;
                if (c0 < c2) continue;                 // nearest pred not ready
                if (c2 < 32) {
                    unsigned val = (lane <= (unsigned)c2) ? (unsigned)d : 0u;
                    prefix += __reduce_add_sync(0xFFFFFFFFu, val);
                    break;
                }
                prefix += __reduce_add_sync(0xFFFFFFFFu, (unsigned)d);
                base -= 32;
            }
            if (lane == 0) {
                atomicExch(&g_desc[tile],
                           (2ull << 32) | (unsigned long long)(prefix + T));
                sh_prefix = prefix;
                if (tile == SCAN_TILES - 1) g_total = prefix + T;
            }
        }
    }
    __syncthreads();

    unsigned base2 = sh_prefix + excl;
    uint4* tp = reinterpret_cast<uint4*>(g_tab + (size_t)t * 4);
    tp[0] = make_uint4(w.x, base2,           w.y, base2 + p0);
    tp[1] = make_uint4(w.z, base2 + p0 + p1, w.w, base2 + p0 + p1 + p2);
}

// ---------------------------------------------------------------------------
// Scatter (owners, streaming stores) + piggyback ranges riding in the
// DRAM-bound window: pad-row zeroing, extras-rank precompute, g_desc reset.
__global__ void k_scatter(const float4* __restrict__ feat,
                          float* __restrict__ out, int n, int nb) {
    if ((int)blockIdx.x < nb) {
        __shared__ unsigned s_rd[256];
        int base = blockIdx.x * 256;
        int p = base + threadIdx.x;
        unsigned rd = 0xFFFFFFFFu;
        if (p < n) {
            unsigned k = __ldcs(&g_key[p]);
            if (!(k & EXTRA_BIT)) {
                unsigned w = k >> 5, b = k & 31;
                uint2 e = __ldg(&g_tab[w]);           // {bits, rank}
                rd = e.y + __popc(e.x & ((1u << b) - 1u));
            }
        }
        s_rd[threadIdx.x] = rd;
        __syncthreads();
        int team = threadIdx.x >> 3;
        int lane = threadIdx.x & 7;
        #pragma unroll
        for (int j = 0; j < 8; j++) {
            int pl = j * 32 + team;
            int pg = base + pl;
            if (pg < n) {
                unsigned r = s_rd[pl];
                if (r != 0xFFFFFFFFu) {
                    float4 v = __ldcs(&feat[(size_t)pg * 8 + lane]);
                    float* dst = out + (size_t)r * 32 + lane * 4;
                    asm volatile("st.global.cs.v4.f32 [%0], {%1,%2,%3,%4};"
                                 :: "l"(dst), "f"(v.x), "f"(v.y), "f"(v.z), "f"(v.w)
                                 : "memory");
                }
            }
        }
    } else if ((int)blockIdx.x < nb + PAD_BLOCKS) {
        // Zero padding rows [g_total, N).
        float4 z = make_float4(0.f, 0.f, 0.f, 0.f);
        size_t start  = (size_t)g_total * 8;
        size_t end    = (size_t)n * 8;
        size_t stride = (size_t)PAD_BLOCKS * 256;
        for (size_t i = start + (size_t)(blockIdx.x - nb) * 256 + threadIdx.x;
             i < end; i += stride)
            reinterpret_cast<float4*>(out)[i] = z;
    } else {
        // Precompute extras ranks; first block also resets scan descriptors.
        if ((int)blockIdx.x == nb + PAD_BLOCKS) {
            g_desc[threadIdx.x * 2]     = 0ull;      // 256 threads x 2 = 512
            g_desc[threadIdx.x * 2 + 1] = 0ull;
        }
        unsigned cnt = g_extra_cnt;
        unsigned stride = EXR_BLOCKS * 256;
        for (unsigned i = (blockIdx.x - nb - PAD_BLOCKS) * 256 + threadIdx.x;
             i < cnt; i += stride) {
            unsigned p = g_ex[i].x;
            unsigned k = g_key[p] & KEYMASK;
            unsigned w = k >> 5, b = k & 31;
            uint2 e = __ldg(&g_tab[w]);
            g_ex[i].y = e.y + __popc(e.x & ((1u << b) - 1u));
        }
    }
}

// ---------------------------------------------------------------------------
// Extras: red.add {point,rank} rows onto owner-written rows.
// Last-finishing block resets the remaining pipeline state for next replay.
__global__ void k_extras(const float4* __restrict__ feat,
                         float* __restrict__ out) {
    unsigned tot = g_extra_cnt * 8u;
    unsigned stride = EX_BLOCKS * 256;
    for (unsigned i = blockIdx.x * 256 + threadIdx.x; i < tot; i += stride) {
        uint2 pr = __ldg(&g_ex[i >> 3]);          // {point, rank}, L2-hot
        int lane = i & 7;
        float4 v = __ldg(&feat[(size_t)pr.x * 8 + lane]);
        float* dst = out + (size_t)pr.y * 32 + lane * 4;
        asm volatile("red.global.add.v4.f32 [%0], {%1,%2,%3,%4};"
                     :: "l"(dst), "f"(v.x), "f"(v.y), "f"(v.z), "f"(v.w)
                     : "memory");
    }
    __syncthreads();
    __shared__ unsigned s_last;
    if (threadIdx.x == 0)
        s_last = (atomicAdd(&g_done, 1u) == (unsigned)(gridDim.x - 1));
    __syncthreads();
    if (s_last && threadIdx.x == 0) {
        g_extra_cnt = 0u;
        g_bar = 0u;
        g_done = 0u;
    }
}

// ---------------------------------------------------------------------------
extern "C" void kernel_launch(void* const* d_in, const int* in_sizes, int n_in,
                              void* d_out, int out_size) {
    const int4*   coords = (const int4*)d_in[0];    // [N,4] int32
    const float4* feat   = (const float4*)d_in[1];  // [N,32] f32
    float* out = (float*)d_out;
    int n  = in_sizes[0] / 4;
    int nb = (n + 255) / 256;

    k_build  <<<SCAN_TILES, SCAN_THREADS>>>(coords, n);
    k_scatter<<<nb + PAD_BLOCKS + EXR_BLOCKS, 256>>>(feat, out, n, nb);
    k_extras <<<EX_BLOCKS, 256>>>(feat, out);
}

// round 12
// speedup vs baseline: 1.0743x; 1.0743x over previous
#include <cuda_runtime.h>
#include <cstdint>

// key = ((x*64+y)*64+z)*64+b  in [0, 2^24)
constexpr int KEYSPACE     = 1 << 24;
constexpr int WORDS        = KEYSPACE / 32;                 // 524288
constexpr int SCAN_THREADS = 256;                           // 4 words/thread
constexpr int SCAN_TILES   = WORDS / (4 * SCAN_THREADS);    // 512
constexpr int SB_PPT       = 4;      // setbits points per thread (atomic MLP)
constexpr int PAD_BLOCKS   = 128;    // pad-zero blocks appended to scatter grid
constexpr int EXR_BLOCKS   = 32;     // extras-rank blocks appended to scatter grid
constexpr int EX_BLOCKS    = 512;    // extras red kernel
constexpr unsigned KEYMASK   = 0x00FFFFFFu;
constexpr unsigned EXTRA_BIT = 0x80000000u;

__device__ unsigned g_bitmap[WORDS];             // presence bits (self-cleaned by scan)
__device__ uint2    g_tab[WORDS];                // {bits, rank}
__device__ unsigned g_key[1 << 20];              // per-point key | EXTRA_BIT
__device__ uint2    g_ex[1 << 20];               // {point index, rank} of non-owner dups
__device__ unsigned long long g_desc[SCAN_TILES];// lookback descriptors (reset in scatter)
__device__ unsigned g_extra_cnt;                 // reset by extras epilogue
__device__ unsigned g_done;                      // extras completion counter
__device__ unsigned g_total;                     // unique voxel count

// ---------------------------------------------------------------------------
__device__ __forceinline__ unsigned make_key(int4 c) {
    return ((unsigned)((c.x * 64 + c.y) * 64 + c.z)) * 64u + (unsigned)c.w;
}

__device__ __forceinline__ unsigned long long ld_relaxed(const unsigned long long* p) {
    unsigned long long v;
    asm volatile("ld.relaxed.gpu.global.u64 %0, [%1];" : "=l"(v) : "l"(p) : "memory");
    return v;
}

// Claim voxels, 4 points per thread: 4 independent atomic chains in flight,
// full-size grid so occupancy stays high (unlike the failed persistent fusion).
__global__ void k_setbits(const int4* __restrict__ coords, int n) {
    int base = (blockIdx.x * blockDim.x + threadIdx.x) * SB_PPT;
    if (base >= n) return;

    unsigned k[SB_PPT];
    #pragma unroll
    for (int j = 0; j < SB_PPT; j++) {
        int i = base + j;
        k[j] = (i < n) ? make_key(__ldg(&coords[i])) : 0xFFFFFFFFu;
    }
    unsigned old[SB_PPT];
    #pragma unroll
    for (int j = 0; j < SB_PPT; j++) {
        if (k[j] != 0xFFFFFFFFu)
            old[j] = atomicOr(&g_bitmap[k[j] >> 5], 1u << (k[j] & 31));
    }
    #pragma unroll
    for (int j = 0; j < SB_PPT; j++) {
        if (k[j] != 0xFFFFFFFFu && (old[j] & (1u << (k[j] & 31)))) {
            k[j] |= EXTRA_BIT;
            g_ex[atomicAdd(&g_extra_cnt, 1u)].x = (unsigned)(base + j);
        }
    }
    if (base + SB_PPT <= n) {
        *reinterpret_cast<uint4*>(&g_key[base]) = make_uint4(k[0], k[1], k[2], k[3]);
    } else {
        for (int j = 0; j < SB_PPT; j++)
            if (base + j < n) g_key[base + j] = k[j];
    }
}

// ---------------------------------------------------------------------------
__device__ __forceinline__ unsigned block_excl_scan(unsigned v, unsigned* sh) {
    unsigned lane = threadIdx.x & 31;
    unsigned wid  = threadIdx.x >> 5;
    unsigned x = v;
    #pragma unroll
    for (int o = 1; o < 32; o <<= 1) {
        unsigned y = __shfl_up_sync(0xFFFFFFFFu, x, o);
        if (lane >= o) x += y;
    }
    if (lane == 31) sh[wid] = x;
    __syncthreads();
    if (wid == 0) {
        unsigned nw = blockDim.x >> 5;
        unsigned w2 = (lane < nw) ? sh[lane] : 0u;
        #pragma unroll
        for (int o = 1; o < 32; o <<= 1) {
            unsigned y = __shfl_up_sync(0xFFFFFFFFu, w2, o);
            if (lane >= o) w2 += y;
        }
        if (lane < nw) sh[lane] = w2;
    }
    __syncthreads();
    unsigned warp_prefix = (wid > 0) ? sh[wid - 1] : 0u;
    return warp_prefix + x - v;   // exclusive
}

// Single-pass prefix-popcount, warp-parallel decoupled lookback.
__global__ void k_scan() {
    __shared__ unsigned sh[32];
    __shared__ unsigned sh_total, sh_prefix;
    unsigned tile = blockIdx.x;
    unsigned t = tile * SCAN_THREADS + threadIdx.x;       // uint4 index
    uint4 w = reinterpret_cast<const uint4*>(g_bitmap)[t];
    reinterpret_cast<uint4*>(g_bitmap)[t] = make_uint4(0u, 0u, 0u, 0u); // self-clean
    unsigned p0 = __popc(w.x), p1 = __popc(w.y), p2 = __popc(w.z), p3 = __popc(w.w);
    unsigned sum  = p0 + p1 + p2 + p3;
    unsigned excl = block_excl_scan(sum, sh);
    if (threadIdx.x == SCAN_THREADS - 1) sh_total = excl + sum;
    __syncthreads();
    unsigned T = sh_total;

    if (threadIdx.x < 32) {
        unsigned lane = threadIdx.x;
        unsigned prefix = 0;
        if (tile == 0) {
            if (lane == 0) {
                atomicExch(&g_desc[0], (2ull << 32) | (unsigned long long)T);
                sh_prefix = 0u;
            }
        } else {
            if (lane == 0)
                atomicExch(&g_desc[tile], (1ull << 32) | (unsigned long long)T);
            int base = (int)tile - 1;
            while (true) {
                int j = base - (int)lane;
                unsigned long long d = (j >= 0) ? ld_relaxed(&g_desc[j]) : (2ull << 32);
                unsigned st = (unsigned)(d >> 32);
                unsigned m2 = __ballot_sync(0xFFFFFFFFu, st == 2u);
                unsigned m0 = __ballot_sync(0xFFFFFFFFu, st == 0u);
                int c2 = m2 ? (__ffs(m2) - 1) : 32;
                int c0 = m0 ? (__ffs(m0) - 1) : 32;
                if (c0 < c2) continue;                 // nearest pred not ready
                if (c2 < 32) {
                    unsigned val = (lane <= (unsigned)c2) ? (unsigned)d : 0u;
                    prefix += __reduce_add_sync(0xFFFFFFFFu, val);
                    break;
                }
                prefix += __reduce_add_sync(0xFFFFFFFFu, (unsigned)d);
                base -= 32;
            }
            if (lane == 0) {
                atomicExch(&g_desc[tile],
                           (2ull << 32) | (unsigned long long)(prefix + T));
                sh_prefix = prefix;
                if (tile == SCAN_TILES - 1) g_total = prefix + T;
            }
        }
    }
    __syncthreads();

    unsigned base = sh_prefix + excl;
    uint4* tp = reinterpret_cast<uint4*>(g_tab + (size_t)t * 4);
    tp[0] = make_uint4(w.x, base,           w.y, base + p0);
    tp[1] = make_uint4(w.z, base + p0 + p1, w.w, base + p0 + p1 + p2);
}

// ---------------------------------------------------------------------------
// Scatter (owners, streaming stores) + piggyback ranges riding in the
// DRAM-bound window: pad-row zeroing, extras-rank precompute, g_desc reset.
__global__ void k_scatter(const float4* __restrict__ feat,
                          float* __restrict__ out, int n, int nb) {
    if ((int)blockIdx.x < nb) {
        __shared__ unsigned s_rd[256];
        int base = blockIdx.x * 256;
        int p = base + threadIdx.x;
        unsigned rd = 0xFFFFFFFFu;
        if (p < n) {
            unsigned k = __ldcs(&g_key[p]);
            if (!(k & EXTRA_BIT)) {
                unsigned w = k >> 5, b = k & 31;
                uint2 e = __ldg(&g_tab[w]);           // {bits, rank}
                rd = e.y + __popc(e.x & ((1u << b) - 1u));
            }
        }
        s_rd[threadIdx.x] = rd;
        __syncthreads();
        int team = threadIdx.x >> 3;
        int lane = threadIdx.x & 7;
        #pragma unroll
        for (int j = 0; j < 8; j++) {
            int pl = j * 32 + team;
            int pg = base + pl;
            if (pg < n) {
                unsigned r = s_rd[pl];
                if (r != 0xFFFFFFFFu) {
                    float4 v = __ldcs(&feat[(size_t)pg * 8 + lane]);
                    float* dst = out + (size_t)r * 32 + lane * 4;
                    asm volatile("st.global.cs.v4.f32 [%0], {%1,%2,%3,%4};"
                                 :: "l"(dst), "f"(v.x), "f"(v.y), "f"(v.z), "f"(v.w)
                                 : "memory");
                }
            }
        }
    } else if ((int)blockIdx.x < nb + PAD_BLOCKS) {
        // Zero padding rows [g_total, N).
        float4 z = make_float4(0.f, 0.f, 0.f, 0.f);
        size_t start  = (size_t)g_total * 8;
        size_t end    = (size_t)n * 8;
        size_t stride = (size_t)PAD_BLOCKS * 256;
        for (size_t i = start + (size_t)(blockIdx.x - nb) * 256 + threadIdx.x;
             i < end; i += stride)
            reinterpret_cast<float4*>(out)[i] = z;
    } else {
        // Precompute extras ranks; first block also resets scan descriptors.
        if ((int)blockIdx.x == nb + PAD_BLOCKS) {
            g_desc[threadIdx.x * 2]     = 0ull;      // 256 threads x 2 = 512
            g_desc[threadIdx.x * 2 + 1] = 0ull;
        }
        unsigned cnt = g_extra_cnt;
        unsigned stride = EXR_BLOCKS * 256;
        for (unsigned i = (blockIdx.x - nb - PAD_BLOCKS) * 256 + threadIdx.x;
             i < cnt; i += stride) {
            unsigned p = g_ex[i].x;
            unsigned k = g_key[p] & KEYMASK;
            unsigned w = k >> 5, b = k & 31;
            uint2 e = __ldg(&g_tab[w]);
            g_ex[i].y = e.y + __popc(e.x & ((1u << b) - 1u));
        }
    }
}

// ---------------------------------------------------------------------------
// Extras: red.add {point,rank} rows onto owner-written rows.
// Last-finishing block resets the remaining pipeline state for next replay.
__global__ void k_extras(const float4* __restrict__ feat,
                         float* __restrict__ out) {
    unsigned tot = g_extra_cnt * 8u;
    unsigned stride = EX_BLOCKS * 256;
    for (unsigned i = blockIdx.x * 256 + threadIdx.x; i < tot; i += stride) {
        uint2 pr = __ldg(&g_ex[i >> 3]);          // {point, rank}, one 8B L2-hot load
        int lane = i & 7;
        float4 v = __ldg(&feat[(size_t)pr.x * 8 + lane]);
        float* dst = out + (size_t)pr.y * 32 + lane * 4;
        asm volatile("red.global.add.v4.f32 [%0], {%1,%2,%3,%4};"
                     :: "l"(dst), "f"(v.x), "f"(v.y), "f"(v.z), "f"(v.w)
                     : "memory");
    }
    __syncthreads();
    __shared__ unsigned s_last;
    if (threadIdx.x == 0)
        s_last = (atomicAdd(&g_done, 1u) == (unsigned)(gridDim.x - 1));
    __syncthreads();
    if (s_last && threadIdx.x == 0) {
        g_extra_cnt = 0u;
        g_done = 0u;
    }
}

// ---------------------------------------------------------------------------
extern "C" void kernel_launch(void* const* d_in, const int* in_sizes, int n_in,
                              void* d_out, int out_size) {
    const int4*   coords = (const int4*)d_in[0];    // [N,4] int32
    const float4* feat   = (const float4*)d_in[1];  // [N,32] f32
    float* out = (float*)d_out;
    int n  = in_sizes[0] / 4;
    int nb = (n + 255) / 256;

    k_setbits<<<(n / SB_PPT + 255) / 256, 256>>>(coords, n);
    k_scan   <<<SCAN_TILES, SCAN_THREADS>>>();
    k_scatter<<<nb + PAD_BLOCKS + EXR_BLOCKS, 256>>>(feat, out, n, nb);
    k_extras <<<EX_BLOCKS, 256>>>(feat, out);
}

// round 13
// speedup vs baseline: 1.2387x; 1.1531x over previous
#include <cuda_runtime.h>
#include <cstdint>

// key = ((x*64+y)*64+z)*64+b  in [0, 2^24)
constexpr int KEYSPACE     = 1 << 24;
constexpr int WORDS        = KEYSPACE / 32;                 // 524288
constexpr int SCAN_THREADS = 256;                           // 4 words/thread
constexpr int SCAN_TILES   = WORDS / (4 * SCAN_THREADS);    // 512
constexpr int SB_PPT       = 4;      // setbits points per thread (atomic MLP)
constexpr int PAD_BLOCKS   = 128;    // pad-zero blocks appended to scatter grid

__device__ unsigned g_bitmap[WORDS];             // presence bits (self-cleaned by scan)
__device__ unsigned g_dup[WORDS];                // dup bits     (self-cleaned by scan)
__device__ uint4    g_tab[WORDS];                // {bits, rank, dup, 0}
__device__ unsigned g_key[1 << 20];              // per-point key
__device__ unsigned long long g_desc[SCAN_TILES];// lookback descriptors (reset in scatter)
__device__ unsigned g_total;                     // unique voxel count

// ---------------------------------------------------------------------------
__device__ __forceinline__ unsigned make_key(int4 c) {
    return ((unsigned)((c.x * 64 + c.y) * 64 + c.z)) * 64u + (unsigned)c.w;
}

__device__ __forceinline__ unsigned long long ld_relaxed(const unsigned long long* p) {
    unsigned long long v;
    asm volatile("ld.relaxed.gpu.global.u64 %0, [%1];" : "=l"(v) : "l"(p) : "memory");
    return v;
}

// Claim voxels, 4 points/thread (atomic MLP=4, full-size grid).
// Second atomicOr marks duplicated voxels (rare, ~3%).
__global__ void k_setbits(const int4* __restrict__ coords, int n) {
    int base = (blockIdx.x * blockDim.x + threadIdx.x) * SB_PPT;
    if (base >= n) return;

    unsigned k[SB_PPT];
    #pragma unroll
    for (int j = 0; j < SB_PPT; j++) {
        int i = base + j;
        k[j] = (i < n) ? make_key(__ldg(&coords[i])) : 0xFFFFFFFFu;
    }
    unsigned old[SB_PPT];
    #pragma unroll
    for (int j = 0; j < SB_PPT; j++) {
        if (k[j] != 0xFFFFFFFFu)
            old[j] = atomicOr(&g_bitmap[k[j] >> 5], 1u << (k[j] & 31));
    }
    #pragma unroll
    for (int j = 0; j < SB_PPT; j++) {
        if (k[j] != 0xFFFFFFFFu && (old[j] & (1u << (k[j] & 31))))
            atomicOr(&g_dup[k[j] >> 5], 1u << (k[j] & 31));
    }
    if (base + SB_PPT <= n) {
        *reinterpret_cast<uint4*>(&g_key[base]) = make_uint4(k[0], k[1], k[2], k[3]);
    } else {
        for (int j = 0; j < SB_PPT; j++)
            if (base + j < n) g_key[base + j] = k[j];
    }
}

// ---------------------------------------------------------------------------
__device__ __forceinline__ unsigned block_excl_scan(unsigned v, unsigned* sh) {
    unsigned lane = threadIdx.x & 31;
    unsigned wid  = threadIdx.x >> 5;
    unsigned x = v;
    #pragma unroll
    for (int o = 1; o < 32; o <<= 1) {
        unsigned y = __shfl_up_sync(0xFFFFFFFFu, x, o);
        if (lane >= o) x += y;
    }
    if (lane == 31) sh[wid] = x;
    __syncthreads();
    if (wid == 0) {
        unsigned nw = blockDim.x >> 5;
        unsigned w2 = (lane < nw) ? sh[lane] : 0u;
        #pragma unroll
        for (int o = 1; o < 32; o <<= 1) {
            unsigned y = __shfl_up_sync(0xFFFFFFFFu, w2, o);
            if (lane >= o) w2 += y;
        }
        if (lane < nw) sh[lane] = w2;
    }
    __syncthreads();
    unsigned warp_prefix = (wid > 0) ? sh[wid - 1] : 0u;
    return warp_prefix + x - v;   // exclusive
}

// Single-pass prefix-popcount (warp-parallel decoupled lookback).
// Also: emits packed table {bits,rank,dup}, zeroes dup-voxel output rows,
// and self-cleans both bitmaps for the next graph replay.
__global__ void k_scan(float4* __restrict__ out) {
    __shared__ unsigned sh[32];
    __shared__ unsigned sh_total, sh_prefix;
    unsigned tile = blockIdx.x;
    unsigned t = tile * SCAN_THREADS + threadIdx.x;       // uint4 index
    uint4 w = reinterpret_cast<const uint4*>(g_bitmap)[t];
    uint4 d = reinterpret_cast<const uint4*>(g_dup)[t];
    reinterpret_cast<uint4*>(g_bitmap)[t] = make_uint4(0u, 0u, 0u, 0u); // self-clean
    reinterpret_cast<uint4*>(g_dup)[t]    = make_uint4(0u, 0u, 0u, 0u);
    unsigned p0 = __popc(w.x), p1 = __popc(w.y), p2 = __popc(w.z), p3 = __popc(w.w);
    unsigned sum  = p0 + p1 + p2 + p3;
    unsigned excl = block_excl_scan(sum, sh);
    if (threadIdx.x == SCAN_THREADS - 1) sh_total = excl + sum;
    __syncthreads();
    unsigned T = sh_total;

    if (threadIdx.x < 32) {
        unsigned lane = threadIdx.x;
        unsigned prefix = 0;
        if (tile == 0) {
            if (lane == 0) {
                atomicExch(&g_desc[0], (2ull << 32) | (unsigned long long)T);
                sh_prefix = 0u;
            }
        } else {
            if (lane == 0)
                atomicExch(&g_desc[tile], (1ull << 32) | (unsigned long long)T);
            int base = (int)tile - 1;
            while (true) {
                int j = base - (int)lane;
                unsigned long long dd = (j >= 0) ? ld_relaxed(&g_desc[j]) : (2ull << 32);
                unsigned st = (unsigned)(dd >> 32);
                unsigned m2 = __ballot_sync(0xFFFFFFFFu, st == 2u);
                unsigned m0 = __ballot_sync(0xFFFFFFFFu, st == 0u);
                int c2 = m2 ? (__ffs(m2) - 1) : 32;
                int c0 = m0 ? (__ffs(m0) - 1) : 32;
                if (c0 < c2) continue;                 // nearest pred not ready
                if (c2 < 32) {
                    unsigned val = (lane <= (unsigned)c2) ? (unsigned)dd : 0u;
                    prefix += __reduce_add_sync(0xFFFFFFFFu, val);
                    break;
                }
                prefix += __reduce_add_sync(0xFFFFFFFFu, (unsigned)dd);
                base -= 32;
            }
            if (lane == 0) {
                atomicExch(&g_desc[tile],
                           (2ull << 32) | (unsigned long long)(prefix + T));
                sh_prefix = prefix;
                if (tile == SCAN_TILES - 1) g_total = prefix + T;
            }
        }
    }
    __syncthreads();

    unsigned base = sh_prefix + excl;
    unsigned rb[4] = { base, base + p0, base + p0 + p1, base + p0 + p1 + p2 };
    unsigned bw[4] = { w.x, w.y, w.z, w.w };
    unsigned dw[4] = { d.x, d.y, d.z, d.w };

    uint4* tp = g_tab + (size_t)t * 4;
    #pragma unroll
    for (int j = 0; j < 4; j++)
        tp[j] = make_uint4(bw[j], rb[j], dw[j], 0u);

    // Zero output rows of duplicated voxels (pre-zeroed for scatter's red.add).
    float4 z = make_float4(0.f, 0.f, 0.f, 0.f);
    #pragma unroll
    for (int j = 0; j < 4; j++) {
        unsigned dm = dw[j];
        while (dm) {
            int b = __ffs(dm) - 1;
            dm &= dm - 1;
            unsigned rank = rb[j] + __popc(bw[j] & ((1u << b) - 1u));
            float4* row = out + (size_t)rank * 8;
            #pragma unroll
            for (int q = 0; q < 8; q++) row[q] = z;
        }
    }
}

// ---------------------------------------------------------------------------
// Scatter: ALL points. Non-dup voxel -> streaming store; dup voxel (owner and
// extras alike) -> red.add onto the row pre-zeroed by k_scan. Piggyback pad
// blocks zero rows [g_total, N) and reset the scan descriptors.
__global__ void k_scatter(const float4* __restrict__ feat,
                          float* __restrict__ out, int n, int nb) {
    if ((int)blockIdx.x < nb) {
        __shared__ unsigned s_rd[256];
        int base = blockIdx.x * 256;
        int p = base + threadIdx.x;
        if (p < n) {
            unsigned k = __ldcs(&g_key[p]);
            unsigned w = k >> 5, b = k & 31;
            uint4 e = __ldg(&g_tab[w]);               // {bits, rank, dup, -}
            unsigned rank = e.y + __popc(e.x & ((1u << b) - 1u));
            s_rd[threadIdx.x] = (rank << 1) | ((e.z >> b) & 1u);
        }
        __syncthreads();
        int team = threadIdx.x >> 3;
        int lane = threadIdx.x & 7;
        #pragma unroll
        for (int j = 0; j < 8; j++) {
            int pl = j * 32 + team;
            int pg = base + pl;
            if (pg < n) {
                unsigned rd = s_rd[pl];
                float4 v = __ldcs(&feat[(size_t)pg * 8 + lane]);
                float* dst = out + (size_t)(rd >> 1) * 32 + lane * 4;
                if (!(rd & 1u)) {
                    asm volatile("st.global.cs.v4.f32 [%0], {%1,%2,%3,%4};"
                                 :: "l"(dst), "f"(v.x), "f"(v.y), "f"(v.z), "f"(v.w)
                                 : "memory");
                } else {
                    asm volatile("red.global.add.v4.f32 [%0], {%1,%2,%3,%4};"
                                 :: "l"(dst), "f"(v.x), "f"(v.y), "f"(v.z), "f"(v.w)
                                 : "memory");
                }
            }
        }
    } else {
        // Pad-zero rows [g_total, N); first pad block also resets descriptors.
        if ((int)blockIdx.x == nb) {
            g_desc[threadIdx.x * 2]     = 0ull;       // 256 threads x 2 = 512
            g_desc[threadIdx.x * 2 + 1] = 0ull;
        }
        float4 z = make_float4(0.f, 0.f, 0.f, 0.f);
        size_t start  = (size_t)g_total * 8;
        size_t end    = (size_t)n * 8;
        size_t stride = (size_t)PAD_BLOCKS * 256;
        for (size_t i = start + (size_t)(blockIdx.x - nb) * 256 + threadIdx.x;
             i < end; i += stride)
            reinterpret_cast<float4*>(out)[i] = z;
    }
}

// ---------------------------------------------------------------------------
extern "C" void kernel_launch(void* const* d_in, const int* in_sizes, int n_in,
                              void* d_out, int out_size) {
    const int4*   coords = (const int4*)d_in[0];    // [N,4] int32
    const float4* feat   = (const float4*)d_in[1];  // [N,32] f32
    float* out = (float*)d_out;
    int n  = in_sizes[0] / 4;
    int nb = (n + 255) / 256;

    k_setbits<<<(n / SB_PPT + 255) / 256, 256>>>(coords, n);
    k_scan   <<<SCAN_TILES, SCAN_THREADS>>>((float4*)d_out);
    k_scatter<<<nb + PAD_BLOCKS, 256>>>(feat, out, n, nb);
}